// round 1
// baseline (speedup 1.0000x reference)
#include <cuda_runtime.h>
#include <math.h>

#define H_IMG      256
#define NUM_V      512
#define NUM_F      1024
#define TPB        256
#define NUM_BLOCKS 256   // one image row per block

// Scratch (no allocations allowed in kernel_launch)
__device__ float4 g_face[NUM_F * 3];          // per-face edge coeffs: (A,B,C,0) x3
__device__ float  g_partial[NUM_BLOCKS * 8];  // per-(block,warp) partial SSE

// ---------------------------------------------------------------------------
// Setup: camera transform + projection + per-edge line coefficients.
// d_i(q) = A_i*qx + B_i*qy + C_i  replicates
// cross*inv_len with  A=-ey*il, B=ex*il, C=(ey*ax-ex*ay)*il.
// ---------------------------------------------------------------------------
__global__ void setup_kernel(const float* __restrict__ verts,
                             const int*   __restrict__ faces,
                             const float* __restrict__ cam)
{
    int f = blockIdx.x * blockDim.x + threadIdx.x;
    if (f >= NUM_F) return;

    float ex = cam[0], ey = cam[1], ez = cam[2];

    // z_axis = normalize(-eye)
    float nx = -ex, ny = -ey, nz = -ez;
    float nl = sqrtf(nx*nx + ny*ny + nz*nz) + 1e-8f;
    float zx = nx/nl, zy = ny/nl, zz = nz/nl;
    // x_axis = normalize(cross(up=(0,1,0), z)) = normalize((zz, 0, -zx))
    float cxx = zz, cxy = 0.0f, cxz = -zx;
    float cl = sqrtf(cxx*cxx + cxy*cxy + cxz*cxz) + 1e-8f;
    float xax = cxx/cl, xay = cxy/cl, xaz = cxz/cl;
    // y_axis = normalize(cross(z, x))
    float yx = zy*xaz - zz*xay;
    float yy = zz*xax - zx*xaz;
    float yz = zx*xay - zy*xax;
    float yl = sqrtf(yx*yx + yy*yy + yz*yz) + 1e-8f;
    yx /= yl; yy /= yl; yz /= yl;

    const float t = 0.57735026918962576f;  // tan(30 deg)

    float sx[3], sy[3];
    bool valid = true;
    #pragma unroll
    for (int k = 0; k < 3; k++) {
        int vi = faces[f*3 + k];
        float px = verts[vi*3 + 0] - ex;
        float py = verts[vi*3 + 1] - ey;
        float pz = verts[vi*3 + 2] - ez;
        float X = px*xax + py*xay + pz*xaz;
        float Y = px*yx  + py*yy  + pz*yz;
        float Z = px*zx  + py*zy  + pz*zz;
        valid = valid && (Z > 0.001f);
        float den = Z*t + 1e-8f;
        sx[k] = X / den;
        sy[k] = Y / den;
    }

    #pragma unroll
    for (int k = 0; k < 3; k++) {
        int a = k;
        int b = (k == 2) ? 0 : (k + 1);
        float eex = sx[b] - sx[a];
        float eey = sy[b] - sy[a];
        float il  = 1.0f / (sqrtf(eex*eex + eey*eey) + 1e-8f);
        float A = -eey * il;
        float B =  eex * il;
        float C = (eey * sx[a] - eex * sy[a]) * il;
        if (!valid) {
            // Sentinel: forces dmin=-1e30, dmax=+1e30 -> dist=-1e30 -> skipped
            A = 0.0f; B = 0.0f;
            C = (k == 2) ? 1e30f : -1e30f;
        }
        g_face[f*3 + k] = make_float4(A, B, C, 0.0f);
    }
}

// ---------------------------------------------------------------------------
// Main raster: one block per image row, one thread per pixel column.
// Fast path: classify dist vs [LO, HI]; only the narrow band pays MUFU.
// ---------------------------------------------------------------------------
__global__ void render_kernel(const float* __restrict__ img)
{
    extern __shared__ float4 sface[];  // NUM_F*3 float4 = 48KB

    int tid = threadIdx.x;
    for (int i = tid; i < NUM_F * 3; i += TPB)
        sface[i] = g_face[i];
    __syncthreads();

    int row = blockIdx.x;
    int col = tid;
    float qx =  ((col + 0.5f) / 256.0f) * 2.0f - 1.0f;
    float qy = -(((row + 0.5f) / 256.0f) * 2.0f - 1.0f);

    // x >= 13.80232  =>  contribution == LOG_EPS exactly (post-clip)
    const float HI      =  0.03716f;      // sqrt(13.80232e-4), rounded up
    const float LO      = -0.0448f;       // x < -20.07 => |contrib| < 2.1e-9
    const float LOG_EPS = -13.8023195f;   // log1p(-(1-1e-6)) in fp32

    float S  = 0.0f;
    int   cnt = 0;

    #pragma unroll 4
    for (int f = 0; f < NUM_F; f++) {
        float4 e0 = sface[3*f + 0];
        float4 e1 = sface[3*f + 1];
        float4 e2 = sface[3*f + 2];
        float d0 = fmaf(e0.x, qx, fmaf(e0.y, qy, e0.z));
        float d1 = fmaf(e1.x, qx, fmaf(e1.y, qy, e1.z));
        float d2 = fmaf(e2.x, qx, fmaf(e2.y, qy, e2.z));
        float dmin = fminf(fminf(d0, d1), d2);
        float dmax = fmaxf(fmaxf(d0, d1), d2);
        float dist = fmaxf(dmin, -dmax);

        if (dist > HI) {
            cnt++;                                   // saturated: exact LOG_EPS
        } else if (dist > LO) {
            float x  = dist * fabsf(dist) * 1e4f;    // dist*|dist|/SIGMA
            float ax = fabsf(x);
            float sp = ax + log1pf(__expf(-ax));     // softplus(|x|)
            float c  = (x > 0.0f) ? -sp : (ax - sp); // -softplus(x)
            S += fmaxf(c, LOG_EPS);                  // prob clip
        }
        // else: contribution < 2.1e-9 in magnitude, skip
    }

    S += (float)cnt * LOG_EPS;
    float alpha = 1.0f - expf(S);
    float r = img[row * H_IMG + col] - alpha;
    float v = r * r;

    // deterministic warp reduce -> per-(row,warp) slot
    #pragma unroll
    for (int o = 16; o > 0; o >>= 1)
        v += __shfl_down_sync(0xffffffffu, v, o);
    if ((tid & 31) == 0)
        g_partial[row * 8 + (tid >> 5)] = v;
}

// ---------------------------------------------------------------------------
// Final deterministic reduce + distance penalty scale.
// ---------------------------------------------------------------------------
__global__ void finish_kernel(const float* __restrict__ cam,
                              float* __restrict__ out)
{
    __shared__ float red[TPB];
    float s = 0.0f;
    for (int i = threadIdx.x; i < NUM_BLOCKS * 8; i += TPB)
        s += g_partial[i];
    red[threadIdx.x] = s;
    __syncthreads();
    #pragma unroll
    for (int o = TPB / 2; o > 0; o >>= 1) {
        if (threadIdx.x < o) red[threadIdx.x] += red[threadIdx.x + o];
        __syncthreads();
    }
    if (threadIdx.x == 0) {
        float d = sqrtf(cam[0]*cam[0] + cam[1]*cam[1] + cam[2]*cam[2]);
        float pen = fmaxf(0.0f, 6.0f - d);
        out[0] = red[0] * (1.0f + pen);
    }
}

// ---------------------------------------------------------------------------
extern "C" void kernel_launch(void* const* d_in, const int* in_sizes, int n_in,
                              void* d_out, int out_size)
{
    const float* verts = nullptr;
    const int*   faces = nullptr;
    const float* img   = nullptr;
    const float* cam   = nullptr;

    for (int i = 0; i < n_in; i++) {
        switch (in_sizes[i]) {
            case NUM_V * 3:      verts = (const float*)d_in[i]; break;
            case NUM_F * 3:      faces = (const int*)  d_in[i]; break;
            case H_IMG * H_IMG:  img   = (const float*)d_in[i]; break;
            case 3:              cam   = (const float*)d_in[i]; break;
            default: break;
        }
    }

    setup_kernel<<<(NUM_F + TPB - 1) / TPB, TPB>>>(verts, faces, cam);

    size_t smem = (size_t)NUM_F * 3 * sizeof(float4);  // 49152 = default limit
    render_kernel<<<NUM_BLOCKS, TPB, smem>>>(img);

    finish_kernel<<<1, TPB>>>(cam, (float*)d_out);
}

// round 2
// speedup vs baseline: 3.7312x; 3.7312x over previous
#include <cuda_runtime.h>
#include <math.h>

#define H_IMG      256
#define NUM_V      512
#define NUM_F      1024
#define TPB        256

#define TILE       16                 // tile edge in pixels
#define NTILES     256                // (256/16)^2
#define NCHUNK     8
#define CHUNK      128                // faces per chunk (NCHUNK*CHUNK = NUM_F)

#define LOG_EPS    (-13.815511f)      // log1p(-(1-1e-6)) in fp32
#define HI_T       (0.03717f)         // dist>HI  => contribution == LOG_EPS exactly
#define LO_T       (-0.0448f)         // dist<LO  => |contribution| < 2.1e-9
#define TILE_R     (0.0830f)          // pixel-center half-diagonal of a 16px tile (7.5*sqrt(2)/128)
#define SKIP_C     (LO_T - TILE_R)    // center-dist below this: whole tile skips face
#define SAT_C      (HI_T + TILE_R)    // center-dist above this: whole tile saturated

// Device scratch (no allocations allowed anywhere)
__device__ float4 g_face[NUM_F * 3];            // per-face edge coeffs (A,B,C,0) x3
__device__ float  g_S[NCHUNK * H_IMG * H_IMG];  // per-(chunk,pixel) partial S, chunk-major
__device__ float  g_partial[NTILES * 8];        // per-(block,warp) partial SSE

// ---------------------------------------------------------------------------
// Setup: camera transform + projection + per-edge line coefficients.
// ---------------------------------------------------------------------------
__global__ void setup_kernel(const float* __restrict__ verts,
                             const int*   __restrict__ faces,
                             const float* __restrict__ cam)
{
    int f = blockIdx.x * blockDim.x + threadIdx.x;
    if (f >= NUM_F) return;

    float ex = cam[0], ey = cam[1], ez = cam[2];

    // z_axis = normalize(-eye)
    float nx = -ex, ny = -ey, nz = -ez;
    float nl = sqrtf(nx*nx + ny*ny + nz*nz) + 1e-8f;
    float zx = nx/nl, zy = ny/nl, zz = nz/nl;
    // x_axis = normalize(cross(up=(0,1,0), z)) = normalize((zz, 0, -zx))
    float cxx = zz, cxz = -zx;
    float cl = sqrtf(cxx*cxx + cxz*cxz) + 1e-8f;
    float xax = cxx/cl, xay = 0.0f, xaz = cxz/cl;
    // y_axis = normalize(cross(z, x))
    float yx = zy*xaz - zz*xay;
    float yy = zz*xax - zx*xaz;
    float yz = zx*xay - zy*xax;
    float yl = sqrtf(yx*yx + yy*yy + yz*yz) + 1e-8f;
    yx /= yl; yy /= yl; yz /= yl;

    const float t = 0.57735026918962576f;  // tan(30 deg)

    float sx[3], sy[3];
    bool valid = true;
    #pragma unroll
    for (int k = 0; k < 3; k++) {
        int vi = faces[f*3 + k];
        float px = verts[vi*3 + 0] - ex;
        float py = verts[vi*3 + 1] - ey;
        float pz = verts[vi*3 + 2] - ez;
        float X = px*xax + py*xay + pz*xaz;
        float Y = px*yx  + py*yy  + pz*yz;
        float Z = px*zx  + py*zy  + pz*zz;
        valid = valid && (Z > 0.001f);
        float den = Z*t + 1e-8f;
        sx[k] = X / den;
        sy[k] = Y / den;
    }

    #pragma unroll
    for (int k = 0; k < 3; k++) {
        int a = k;
        int b = (k == 2) ? 0 : (k + 1);
        float eex = sx[b] - sx[a];
        float eey = sy[b] - sy[a];
        float il  = 1.0f / (sqrtf(eex*eex + eey*eey) + 1e-8f);
        float A = -eey * il;
        float B =  eex * il;
        float C = (eey * sx[a] - eex * sy[a]) * il;
        if (!valid) {
            // Sentinel: dmin=-1e30, dmax=+1e30 -> dist=-1e30 -> always skipped
            A = 0.0f; B = 0.0f;
            C = (k == 2) ? 1e30f : -1e30f;
        }
        g_face[f*3 + k] = make_float4(A, B, C, 0.0f);
    }
}

__device__ __forceinline__ float face_dist(const float4 e0, const float4 e1,
                                           const float4 e2, float qx, float qy)
{
    float d0 = fmaf(e0.x, qx, fmaf(e0.y, qy, e0.z));
    float d1 = fmaf(e1.x, qx, fmaf(e1.y, qy, e1.z));
    float d2 = fmaf(e2.x, qx, fmaf(e2.y, qy, e2.z));
    float dmin = fminf(fminf(d0, d1), d2);
    float dmax = fmaxf(fmaxf(d0, d1), d2);
    return fmaxf(dmin, -dmax);
}

// ---------------------------------------------------------------------------
// Render: grid (NTILES, NCHUNK). One block = one 16x16 pixel tile x 128 faces.
// Phase 1: Lipschitz tile classification (skip / saturated / band-list) via
//          deterministic warp-ballot compaction.
// Phase 2: per-pixel loop over the (usually tiny) band list.
// ---------------------------------------------------------------------------
__global__ void render_kernel()
{
    __shared__ float4 sf[CHUNK * 3];     // 6 KB
    __shared__ int    slist[CHUNK];      // band-face local indices, per-warp segments
    __shared__ int    wcnt[4];
    __shared__ int    wsat[4];

    const int tid = threadIdx.x;
    const int t   = blockIdx.x;          // tile id
    const int c   = blockIdx.y;          // face chunk id

    // Load this chunk's face coeffs into shared
    #pragma unroll
    for (int i = tid; i < CHUNK * 3; i += TPB)
        sf[i] = g_face[c * CHUNK * 3 + i];
    __syncthreads();

    const int tx = t & 15, ty = t >> 4;
    // tile center in NDC (pixel-center convention)
    const float cx =  ((tx * 16 + 8.0f) / 128.0f) - 1.0f;
    const float cy = -(((ty * 16 + 8.0f) / 128.0f) - 1.0f);

    const int w = tid >> 5, lane = tid & 31;

    // Phase 1: warps 0-3 classify 32 faces each (faces w*32+lane)
    if (w < 4) {
        int fi = w * 32 + lane;
        float dc = face_dist(sf[3*fi], sf[3*fi+1], sf[3*fi+2], cx, cy);
        bool sat  = (dc > SAT_C);
        bool band = (dc > SKIP_C) && !sat;
        unsigned mb = __ballot_sync(0xffffffffu, band);
        unsigned ms = __ballot_sync(0xffffffffu, sat);
        if (band) {
            int pos = __popc(mb & ((1u << lane) - 1u));
            slist[w * 32 + pos] = fi;
        }
        if (lane == 0) {
            wcnt[w] = __popc(mb);
            wsat[w] = __popc(ms);
        }
    }
    __syncthreads();

    const int sat_total = wsat[0] + wsat[1] + wsat[2] + wsat[3];

    // Phase 2: per-pixel evaluation over band list (uniform bounds per block)
    const int col = tx * 16 + (tid & 15);
    const int row = ty * 16 + (tid >> 4);
    const float qx =  ((col + 0.5f) / 128.0f) - 1.0f;
    const float qy = -(((row + 0.5f) / 128.0f) - 1.0f);

    float S   = 0.0f;
    int   cnt = sat_total;

    #pragma unroll 1
    for (int ww = 0; ww < 4; ww++) {
        const int n = wcnt[ww];
        for (int j = 0; j < n; j++) {
            int fi = slist[ww * 32 + j];
            float dist = face_dist(sf[3*fi], sf[3*fi+1], sf[3*fi+2], qx, qy);
            if (dist > HI_T) {
                cnt++;
            } else if (dist > LO_T) {
                float x  = dist * fabsf(dist) * 1e4f;
                float ax = fabsf(x);
                float sp = ax + log1pf(__expf(-ax));     // softplus(|x|)
                float cc = (x > 0.0f) ? -sp : (ax - sp); // -softplus(x)
                S += fmaxf(cc, LOG_EPS);
            }
        }
    }

    S += (float)cnt * LOG_EPS;
    g_S[c * (H_IMG * H_IMG) + row * H_IMG + col] = S;
}

// ---------------------------------------------------------------------------
// Combine: fixed-order sum over chunks, alpha, SSE vs image_ref, block reduce.
// ---------------------------------------------------------------------------
__global__ void combine_kernel(const float* __restrict__ img)
{
    const int pix = blockIdx.x * TPB + threadIdx.x;

    float S = 0.0f;
    #pragma unroll
    for (int c = 0; c < NCHUNK; c++)
        S += g_S[c * (H_IMG * H_IMG) + pix];

    float alpha = 1.0f - expf(S);
    float r = img[pix] - alpha;
    float v = r * r;

    #pragma unroll
    for (int o = 16; o > 0; o >>= 1)
        v += __shfl_down_sync(0xffffffffu, v, o);
    if ((threadIdx.x & 31) == 0)
        g_partial[blockIdx.x * 8 + (threadIdx.x >> 5)] = v;
}

// ---------------------------------------------------------------------------
// Final deterministic reduce + distance penalty scale.
// ---------------------------------------------------------------------------
__global__ void finish_kernel(const float* __restrict__ cam,
                              float* __restrict__ out)
{
    __shared__ float red[TPB];
    float s = 0.0f;
    for (int i = threadIdx.x; i < NTILES * 8; i += TPB)
        s += g_partial[i];
    red[threadIdx.x] = s;
    __syncthreads();
    #pragma unroll
    for (int o = TPB / 2; o > 0; o >>= 1) {
        if (threadIdx.x < o) red[threadIdx.x] += red[threadIdx.x + o];
        __syncthreads();
    }
    if (threadIdx.x == 0) {
        float d = sqrtf(cam[0]*cam[0] + cam[1]*cam[1] + cam[2]*cam[2]);
        float pen = fmaxf(0.0f, 6.0f - d);
        out[0] = red[0] * (1.0f + pen);
    }
}

// ---------------------------------------------------------------------------
extern "C" void kernel_launch(void* const* d_in, const int* in_sizes, int n_in,
                              void* d_out, int out_size)
{
    const float* verts = nullptr;
    const int*   faces = nullptr;
    const float* img   = nullptr;
    const float* cam   = nullptr;

    for (int i = 0; i < n_in; i++) {
        switch (in_sizes[i]) {
            case NUM_V * 3:      verts = (const float*)d_in[i]; break;
            case NUM_F * 3:      faces = (const int*)  d_in[i]; break;
            case H_IMG * H_IMG:  img   = (const float*)d_in[i]; break;
            case 3:              cam   = (const float*)d_in[i]; break;
            default: break;
        }
    }

    setup_kernel<<<(NUM_F + TPB - 1) / TPB, TPB>>>(verts, faces, cam);

    dim3 rgrid(NTILES, NCHUNK);
    render_kernel<<<rgrid, TPB>>>();

    combine_kernel<<<(H_IMG * H_IMG) / TPB, TPB>>>(img);

    finish_kernel<<<1, TPB>>>(cam, (float*)d_out);
}

// round 3
// speedup vs baseline: 4.3737x; 1.1722x over previous
#include <cuda_runtime.h>
#include <math.h>

#define H_IMG   256
#define NUM_V   512
#define NUM_F   1024
#define TPB     256

#define NTILES  256                  // (256/16)^2 tiles of 16x16 px
#define NCHUNK  16
#define CHUNK   64                   // faces per chunk

#define LOG_EPS (-13.815511f)        // log(1e-6) = log1p(-(1-1e-6))
#define HI_T    (0.03717f)           // dist>HI  => contribution == LOG_EPS exactly
#define LO_T    (-0.0448f)           // dist<LO  => |contribution| < 2.1e-9
#define TILE_R  (0.0830f)            // pixel-center half-diagonal of 16px tile
#define SKIP_C  (LO_T - TILE_R)
#define SAT_C   (HI_T + TILE_R)

// Device scratch (no allocations anywhere)
__device__ float g_S[NCHUNK * H_IMG * H_IMG];  // per-(chunk,pixel) partial S
__device__ float g_partial[NTILES];            // per-combine-block SSE partial
__device__ int   g_counter;                    // last-block election

__device__ __forceinline__ float face_dist(const float4 e0, const float4 e1,
                                           const float4 e2, float qx, float qy)
{
    float d0 = fmaf(e0.x, qx, fmaf(e0.y, qy, e0.z));
    float d1 = fmaf(e1.x, qx, fmaf(e1.y, qy, e1.z));
    float d2 = fmaf(e2.x, qx, fmaf(e2.y, qy, e2.z));
    float dmin = fminf(fminf(d0, d1), d2);
    float dmax = fmaxf(fmaxf(d0, d1), d2);
    return fmaxf(dmin, -dmax);
}

// ---------------------------------------------------------------------------
// K1: fused setup + render. Grid (NTILES, NCHUNK).
// Each block projects its own 64-face chunk (threads 0..63, ~1.2us chip-wide
// total redundancy), classifies them against its 16x16 tile via the Lipschitz
// bound, then runs the per-pixel loop over the surviving band list.
// ---------------------------------------------------------------------------
__global__ void __launch_bounds__(TPB)
render_kernel(const float* __restrict__ verts,
              const int*   __restrict__ faces,
              const float* __restrict__ cam)
{
    __shared__ float4 sf[CHUNK * 3];   // 3 KB: per-edge (A,B,C,_)
    __shared__ int    slist[CHUNK];
    __shared__ int    wcnt[2];
    __shared__ int    wsat[2];

    const int tid  = threadIdx.x;
    const int tile = blockIdx.x;
    const int c    = blockIdx.y;

    if (tile == 0 && c == 0 && tid == 0) g_counter = 0;   // reset election

    // ---- per-block setup of this chunk's 64 faces ----
    if (tid < CHUNK) {
        const int f = c * CHUNK + tid;

        float ex = cam[0], ey = cam[1], ez = cam[2];

        // camera basis
        float nl = sqrtf(ex*ex + ey*ey + ez*ez) + 1e-8f;
        float zx = -ex/nl, zy = -ey/nl, zz = -ez/nl;
        float cl = sqrtf(zz*zz + zx*zx) + 1e-8f;
        float xax = zz/cl, xay = 0.0f, xaz = -zx/cl;   // normalize(cross(up,z))
        float yx = zy*xaz - zz*xay;
        float yy = zz*xax - zx*xaz;
        float yz = zx*xay - zy*xax;
        float yl = sqrtf(yx*yx + yy*yy + yz*yz) + 1e-8f;
        yx /= yl; yy /= yl; yz /= yl;

        const float t = 0.57735026918962576f;  // tan(30deg)

        float sx[3], sy[3];
        bool valid = true;
        #pragma unroll
        for (int k = 0; k < 3; k++) {
            int vi = faces[f*3 + k];
            float px = verts[vi*3 + 0] - ex;
            float py = verts[vi*3 + 1] - ey;
            float pz = verts[vi*3 + 2] - ez;
            float X = px*xax + py*xay + pz*xaz;
            float Y = px*yx  + py*yy  + pz*yz;
            float Z = px*zx  + py*zy  + pz*zz;
            valid = valid && (Z > 0.001f);
            float den = Z*t + 1e-8f;
            sx[k] = X / den;
            sy[k] = Y / den;
        }

        #pragma unroll
        for (int k = 0; k < 3; k++) {
            int a = k;
            int b = (k == 2) ? 0 : (k + 1);
            float eex = sx[b] - sx[a];
            float eey = sy[b] - sy[a];
            float il  = 1.0f / (sqrtf(eex*eex + eey*eey) + 1e-8f);
            float A = -eey * il;
            float B =  eex * il;
            float C = (eey * sx[a] - eex * sy[a]) * il;
            if (!valid) {           // sentinel: dist = -1e30 -> always skipped
                A = 0.0f; B = 0.0f;
                C = (k == 2) ? 1e30f : -1e30f;
            }
            sf[tid*3 + k] = make_float4(A, B, C, 0.0f);
        }
    }
    __syncthreads();

    // ---- tile classification (Lipschitz: dist is 1-Lipschitz in q) ----
    const int tx = tile & 15, ty = tile >> 4;
    const float cx =  ((tx * 16 + 8.0f) / 128.0f) - 1.0f;
    const float cy = -(((ty * 16 + 8.0f) / 128.0f) - 1.0f);

    const int w = tid >> 5, lane = tid & 31;
    if (w < 2) {
        int fi = w * 32 + lane;
        float dc = face_dist(sf[3*fi], sf[3*fi+1], sf[3*fi+2], cx, cy);
        bool sat  = (dc > SAT_C);
        bool band = (dc > SKIP_C) && !sat;
        unsigned mb = __ballot_sync(0xffffffffu, band);
        unsigned ms = __ballot_sync(0xffffffffu, sat);
        if (band) {
            int pos = __popc(mb & ((1u << lane) - 1u));
            slist[w * 32 + pos] = fi;
        }
        if (lane == 0) {
            wcnt[w] = __popc(mb);
            wsat[w] = __popc(ms);
        }
    }
    __syncthreads();

    const int sat_total = wsat[0] + wsat[1];

    // ---- per-pixel evaluation over band list ----
    const int col = tx * 16 + (tid & 15);
    const int row = ty * 16 + (tid >> 4);
    const float qx =  ((col + 0.5f) / 128.0f) - 1.0f;
    const float qy = -(((row + 0.5f) / 128.0f) - 1.0f);

    float S   = 0.0f;
    int   cnt = sat_total;

    #pragma unroll 1
    for (int ww = 0; ww < 2; ww++) {
        const int n = wcnt[ww];
        for (int j = 0; j < n; j++) {
            int fi = slist[ww * 32 + j];
            float dist = face_dist(sf[3*fi], sf[3*fi+1], sf[3*fi+2], qx, qy);
            if (dist > HI_T) {
                cnt++;
            } else if (dist > LO_T) {
                float x  = dist * fabsf(dist) * 1e4f;
                float ax = fabsf(x);
                float sp = ax + log1pf(__expf(-ax));     // softplus(|x|)
                float cc = (x > 0.0f) ? -sp : (ax - sp); // -softplus(x)
                S += fmaxf(cc, LOG_EPS);
            }
        }
    }

    S += (float)cnt * LOG_EPS;
    g_S[c * (H_IMG * H_IMG) + row * H_IMG + col] = S;
}

// ---------------------------------------------------------------------------
// K2: combine + finish (last-block election; fully deterministic sums).
// ---------------------------------------------------------------------------
__global__ void __launch_bounds__(TPB)
combine_kernel(const float* __restrict__ img,
               const float* __restrict__ cam,
               float* __restrict__ out)
{
    __shared__ float red[8];
    __shared__ int   is_last;

    const int tid = threadIdx.x;
    const int pix = blockIdx.x * TPB + tid;

    float S = 0.0f;
    #pragma unroll
    for (int c = 0; c < NCHUNK; c++)
        S += g_S[c * (H_IMG * H_IMG) + pix];

    float alpha = 1.0f - expf(S);
    float r = img[pix] - alpha;
    float v = r * r;

    #pragma unroll
    for (int o = 16; o > 0; o >>= 1)
        v += __shfl_down_sync(0xffffffffu, v, o);
    if ((tid & 31) == 0) red[tid >> 5] = v;
    __syncthreads();

    if (tid == 0) {
        float bs = 0.0f;
        #pragma unroll
        for (int i = 0; i < 8; i++) bs += red[i];   // fixed order
        g_partial[blockIdx.x] = bs;
        __threadfence();
        int old = atomicAdd(&g_counter, 1);
        is_last = (old == NTILES - 1);
    }
    __syncthreads();

    if (is_last) {
        __threadfence();
        __shared__ float fred[TPB];
        fred[tid] = g_partial[tid];                 // NTILES == TPB == 256
        __syncthreads();
        #pragma unroll
        for (int o = TPB / 2; o > 0; o >>= 1) {     // fixed-order tree
            if (tid < o) fred[tid] += fred[tid + o];
            __syncthreads();
        }
        if (tid == 0) {
            float d = sqrtf(cam[0]*cam[0] + cam[1]*cam[1] + cam[2]*cam[2]);
            float pen = fmaxf(0.0f, 6.0f - d);
            out[0] = fred[0] * (1.0f + pen);
        }
    }
}

// ---------------------------------------------------------------------------
extern "C" void kernel_launch(void* const* d_in, const int* in_sizes, int n_in,
                              void* d_out, int out_size)
{
    const float* verts = nullptr;
    const int*   faces = nullptr;
    const float* img   = nullptr;
    const float* cam   = nullptr;

    for (int i = 0; i < n_in; i++) {
        switch (in_sizes[i]) {
            case NUM_V * 3:      verts = (const float*)d_in[i]; break;
            case NUM_F * 3:      faces = (const int*)  d_in[i]; break;
            case H_IMG * H_IMG:  img   = (const float*)d_in[i]; break;
            case 3:              cam   = (const float*)d_in[i]; break;
            default: break;
        }
    }

    dim3 rgrid(NTILES, NCHUNK);
    render_kernel<<<rgrid, TPB>>>(verts, faces, cam);

    combine_kernel<<<(H_IMG * H_IMG) / TPB, TPB>>>(img, cam, (float*)d_out);
}